// round 9
// baseline (speedup 1.0000x reference)
#include <cuda_runtime.h>
#include <cstdint>

// Scratch: pooled means [8 batches x 128 channels]
__device__ float g_pooled[1024];

// Per-batch completion counters on distinct 128B L2 lines.
struct __align__(128) PadCnt { unsigned int v; unsigned int pad[31]; };
__device__ PadCnt g_cnt_batch[8];

__device__ __forceinline__ float ldg_nc_f32(const float* p) {
    float v;
    asm volatile("ld.global.nc.L2::256B.f32 %0, [%1];" : "=f"(v) : "l"(p));
    return v;
}

__device__ __forceinline__ void prefetch_l2(const void* p) {
    asm volatile("prefetch.global.L2 [%0];" :: "l"(p));
}

// 1024 blocks x 256 threads; one 256x256 plane per block (blk = b*128 + c).
// Phase A: pooled[blk] = mean over even h, even w, via scalar even-float loads:
//   even-elem e (0..16383): row r = e>>7, col c = (e&127)*2
//   thread t handles e = t + u*256  =>  c fixed per thread, r += 2 per u
//   => per-thread address = base + (t&127)*8 + ((t>>7) + 2u)*2048  (stride 4096)
// Phase B: 128th-arriving block of each batch computes that batch's MLP slice.
__global__ __launch_bounds__(256) void fused_kernel(const float* __restrict__ bsrc,
                                                    const float* __restrict__ fc1_w,
                                                    const float* __restrict__ fc2_w,
                                                    float* __restrict__ out) {
    const int blk = blockIdx.x;                    // 0..1023
    const int tid = threadIdx.x;
    const int bb  = blk >> 7;                      // batch 0..7

    // Warm L2 with FC weights (2 x 16 KB) so batch tails hit L2, not DRAM.
    if (blk == 0) {
        prefetch_l2((const char*)fc1_w + tid * 64);
        prefetch_l2((const char*)fc2_w + tid * 64);
    }

    // ---------- Phase A ----------
    // Per-thread base: plane + even-col byte + starting even-row byte.
    const char* __restrict__ tb = (const char*)bsrc
        + ((size_t)blk << 18)                      // plane = 256 KB
        + ((tid & 127) << 3)                       // even-float col, 8 B stride
        + ((tid >> 7) << 11);                      // row 0 or row 2 (2048 B)

    float a0 = 0.f, a1 = 0.f, a2 = 0.f, a3 = 0.f;
    #pragma unroll
    for (int kk = 0; kk < 64; kk += 16) {
        float v[16];
        #pragma unroll
        for (int u = 0; u < 16; ++u)
            v[u] = ldg_nc_f32((const float*)(tb + (size_t)(kk + u) * 4096));
        #pragma unroll
        for (int u = 0; u < 16; u += 4) {
            a0 += v[u + 0];
            a1 += v[u + 1];
            a2 += v[u + 2];
            a3 += v[u + 3];
        }
    }
    float acc = (a0 + a1) + (a2 + a3);

    #pragma unroll
    for (int off = 16; off > 0; off >>= 1)
        acc += __shfl_xor_sync(0xFFFFFFFFu, acc, off);

    __shared__ float warp_sums[8];
    __shared__ int is_batch_last;
    if ((tid & 31) == 0) warp_sums[tid >> 5] = acc;
    if (tid == 0) is_batch_last = 0;
    __syncthreads();

    if (tid == 0) {
        float s = warp_sums[0];
        #pragma unroll
        for (int w = 1; w < 8; ++w) s += warp_sums[w];
        g_pooled[blk] = s * (1.0f / 65536.0f);
        __threadfence();                           // publish before counting

        unsigned int old = atomicAdd(&g_cnt_batch[bb].v, 1u);
        if (old == 127u) {
            g_cnt_batch[bb].v = 0u;                // reset for next graph replay
            is_batch_last = 1;
        }
    }
    __syncthreads();
    if (!is_batch_last) return;

    // ---------- Phase B: this batch's slice of the MLP ----------
    __shared__ __align__(16) float sp[128];        // pooled[bb][0..127]
    __shared__ __align__(16) float sh[32];         // hidden[bb][0..31]

    if (tid < 128) sp[tid] = __ldcg(&g_pooled[(bb << 7) + tid]);
    __syncthreads();

    // hidden[j] = relu( sum_c sp[c] * fc1_w[j][c] ), 8 threads per unit j.
    {
        const int j = tid >> 3;                    // hidden unit 0..31
        const int k = tid & 7;                     // sub-lane, 16 channels each
        const float4* __restrict__ w4 = reinterpret_cast<const float4*>(fc1_w) + j * 32 + k * 4;
        const float4* __restrict__ p4 = reinterpret_cast<const float4*>(sp) + k * 4;
        float s = 0.0f;
        #pragma unroll
        for (int q = 0; q < 4; ++q) {
            float4 w = __ldg(&w4[q]);
            float4 p = p4[q];
            s = fmaf(w.x, p.x, s);
            s = fmaf(w.y, p.y, s);
            s = fmaf(w.z, p.z, s);
            s = fmaf(w.w, p.w, s);
        }
        s += __shfl_xor_sync(0xFFFFFFFFu, s, 4);
        s += __shfl_xor_sync(0xFFFFFFFFu, s, 2);
        s += __shfl_xor_sync(0xFFFFFFFFu, s, 1);
        if (k == 0) sh[j] = fmaxf(s, 0.0f);
    }
    __syncthreads();

    // out[bb*128 + c] = sum_j sh[j] * fc2_w[c][j]; threads 0..127, one output each.
    if (tid < 128) {
        const float4* __restrict__ w4 = reinterpret_cast<const float4*>(fc2_w) + tid * 8;
        const float4* __restrict__ h4 = reinterpret_cast<const float4*>(sh);
        float s = 0.0f;
        #pragma unroll
        for (int q = 0; q < 8; ++q) {
            float4 w = __ldg(&w4[q]);
            float4 h = h4[q];
            s = fmaf(w.x, h.x, s);
            s = fmaf(w.y, h.y, s);
            s = fmaf(w.z, h.z, s);
            s = fmaf(w.w, h.w, s);
        }
        out[(bb << 7) + tid] = s;
    }
}

extern "C" void kernel_launch(void* const* d_in, const int* in_sizes, int n_in,
                              void* d_out, int out_size) {
    // metadata order: a, b, attn_w, attn_b, fc1_w, fc2_w
    const float* bsrc  = (const float*)d_in[1];
    const float* fc1_w = (const float*)d_in[4];
    const float* fc2_w = (const float*)d_in[5];
    float* out = (float*)d_out;

    fused_kernel<<<1024, 256>>>(bsrc, fc1_w, fc2_w, out);
}